// round 8
// baseline (speedup 1.0000x reference)
#include <cuda_runtime.h>
#include <cuda_bf16.h>
#include <cstdint>

#define IMG   4096
#define OUT   4097
#define TX    128
#define TY    32
#define HP    (TX + 3)   // 131  hist-tile pitch (u64)
#define HR    (TY + 3)   // 35   hist-tile rows
#define OPLANE (OUT * OUT)
#define HTY   (TY / 2)

typedef unsigned long long u64;
typedef unsigned int       u32;

// predicated packed add: if (pm == P) acc += v  (two fp32 lanes at once)
#define PRED_ADD2(acc, pm, P, v)                                              \
    asm("{ .reg .pred p; setp.eq.u32 p, %1, %2; @p add.rn.f32x2 %0, %0, %3; }" \
        : "+l"(acc) : "r"(pm), "n"(P), "l"(v))

#define ADD2(d, a, b)                                                         \
    asm("add.rn.f32x2 %0, %1, %2;" : "=l"(d) : "l"(a), "l"(b))

#define FMA2(d, a, b, c)                                                      \
    asm("fma.rn.f32x2 %0, %1, %2, %3;" : "=l"(d) : "l"(a), "l"(b), "l"(c))

// route one hist row (4 packed pixels) into rs[4] (accumulating)
static __device__ __forceinline__ void accum_row(const u64* __restrict__ p, u64 rs[4]) {
#pragma unroll
    for (int j = 0; j < 4; ++j) {
        u64 h  = p[j];
        u32 pm = (u32)h & 3u;           // pair index in low 2 bits of lo lane
        PRED_ADD2(rs[0], pm, 0, h);
        PRED_ADD2(rs[1], pm, 1, h);
        PRED_ADD2(rs[2], pm, 2, h);
        PRED_ADD2(rs[3], pm, 3, h);
    }
}

// sobel + octant + pack from 9 window taps (a11 unused by sobel)
static __device__ __forceinline__ u64 pack_hist(
    float a00, float a01, float a02,
    float a10,             float a12,
    float a20, float a21, float a22)
{
    float S0 = a00 + 2.0f * a10 + a20;
    float S2 = a02 + 2.0f * a12 + a22;
    float D0 = a20 - a00;
    float D1 = a21 - a01;
    float D2 = a22 - a02;
    float dx = S2 - S0;
    float dy = D0 + 2.0f * D1 + D2;

    float sq = dx * dx + dy * dy;
    float sg = fmaxf(sq, 1.17549435e-38f);
    float rs_;
    asm("rsqrt.approx.f32 %0, %1;" : "=f"(rs_) : "f"(sg));
    float mag = sq * rs_;

    // octant of atan2(dy,dx) via sign bits + |dy|>|dx|; tie rules match
    // strict-> first-occurrence argmax of the 8 cosine projections.
    u32 bx = __float_as_uint(dx);
    u32 by = __float_as_uint(dy);
    u32 b2 = by >> 31;
    u32 b1 = (bx ^ by) >> 31;
    u32 c  = (fabsf(dy) > fabsf(dx)) ? 1u : 0u;
    u32 b0 = c ^ b1;
    u32 idx = (b2 << 2) | (b1 << 1) | b0;

    u32 magb = __float_as_uint(mag) & 0xFFFFFFFCu;
    u32 pm   = idx >> 1;
    u32 lo, hi;
    if (idx & 1) { lo = pm;        hi = magb; }
    else         { lo = magb | pm; hi = 0u;   }
    return ((u64)hi << 32) | lo;
}

static __device__ __forceinline__ float ldz(const float* __restrict__ x, int gy, int gx) {
    return ((unsigned)gy < (unsigned)IMG && (unsigned)gx < (unsigned)IMG)
           ? x[gy * IMG + gx] : 0.0f;
}

__global__ __launch_bounds__(256, 5)
void sift_fused8_kernel(const float* __restrict__ x, float* __restrict__ out)
{
    __shared__ u64 hs[HR * HP];   // 36,680 B

    const int tid = threadIdx.x;
    const int ox0 = blockIdx.x * TX;
    const int oy0 = blockIdx.y * TY;

    // ---- phase 1+2 fused: sobel straight from GMEM (L1-resident tile)
    // Hist pixel (hy,hx) center = (gy,gx) = (oy0-2+hy, ox0-2+hx); taps at +-1.
    const bool interior = (ox0 >= 3) && (ox0 + TX + 3 <= IMG) &&
                          (oy0 >= 3) && (oy0 + TY + 3 <= IMG);
    if (interior) {
        for (int e = tid; e < HR * HP; e += 256) {
            int hy = e / HP;
            int hx = e - hy * HP;
            const float* p = x + (oy0 - 3 + hy) * IMG + (ox0 - 3 + hx);
            hs[e] = pack_hist(p[0],       p[1],           p[2],
                              p[IMG],                     p[IMG + 2],
                              p[2 * IMG], p[2 * IMG + 1], p[2 * IMG + 2]);
        }
    } else {
        for (int e = tid; e < HR * HP; e += 256) {
            int hy = e / HP;
            int hx = e - hy * HP;
            int gy = oy0 - 2 + hy;
            int gx = ox0 - 2 + hx;
            u64 pv = 0ull;
            if ((unsigned)gy < (unsigned)IMG && (unsigned)gx < (unsigned)IMG)
                pv = pack_hist(ldz(x, gy - 1, gx - 1), ldz(x, gy - 1, gx), ldz(x, gy - 1, gx + 1),
                               ldz(x, gy,     gx - 1),                     ldz(x, gy,     gx + 1),
                               ldz(x, gy + 1, gx - 1), ldz(x, gy + 1, gx), ldz(x, gy + 1, gx + 1));
            hs[e] = pv;
        }
    }
    __syncthreads();

    // ---- phase 3: 4x4 box sum, vertical sliding window, 4 packed-pair channels
    const int tx   = tid & (TX - 1);
    const int q    = tid >> 7;              // 0/1 -> tile half in y
    const int ox   = ox0 + tx;
    const int oy_s = oy0 + q * HTY;
    const bool oxok = (ox < OUT);
    const u64* hb = hs + tx;
    const int hy0 = q * HTY;

    const u64 NEG1 = 0xBF800000BF800000ull;  // {-1.0f, -1.0f}

    u64 row[4][4];
    u64 acc[4];
#pragma unroll
    for (int pp = 0; pp < 4; ++pp) acc[pp] = 0ull;
#pragma unroll
    for (int k = 0; k < 4; ++k) {
#pragma unroll
        for (int pp = 0; pp < 4; ++pp) row[k][pp] = 0ull;
        accum_row(hb + (hy0 + k) * HP, row[k]);
#pragma unroll
        for (int pp = 0; pp < 4; ++pp) ADD2(acc[pp], acc[pp], row[k][pp]);
    }

#pragma unroll 4
    for (int i = 0; i < HTY; ++i) {
        int oy = oy_s + i;
        if (oxok && oy < OUT) {
            int base = oy * OUT + ox;
#pragma unroll
            for (int pp = 0; pp < 4; ++pp) {
                u32 lo = (u32)acc[pp];
                u32 hi = (u32)(acc[pp] >> 32);
                out[(2 * pp)     * OPLANE + base] = __uint_as_float(lo);
                out[(2 * pp + 1) * OPLANE + base] = __uint_as_float(hi);
            }
        }
        if (i < HTY - 1) {
            u64 nr[4];
#pragma unroll
            for (int pp = 0; pp < 4; ++pp) nr[pp] = 0ull;
            accum_row(hb + (hy0 + 4 + i) * HP, nr);
            const int k = i & 3;
#pragma unroll
            for (int pp = 0; pp < 4; ++pp) {
                u64 t;
                ADD2(t, acc[pp], nr[pp]);            // acc + new
                FMA2(acc[pp], row[k][pp], NEG1, t);  // - old
                row[k][pp] = nr[pp];
            }
        }
    }
}

extern "C" void kernel_launch(void* const* d_in, const int* in_sizes, int n_in,
                              void* d_out, int out_size)
{
    (void)in_sizes; (void)n_in; (void)out_size;
    const float* x = (const float*)d_in[0];
    float* out = (float*)d_out;
    dim3 grid((OUT + TX - 1) / TX, (OUT + TY - 1) / TY);  // 33 x 129
    sift_fused8_kernel<<<grid, 256>>>(x, out);
}

// round 9
// speedup vs baseline: 1.3086x; 1.3086x over previous
#include <cuda_runtime.h>
#include <cuda_bf16.h>
#include <cstdint>

#define IMG   4096
#define OUT   4097
#define TX    128
#define TY    32
#define XP2   136        // x-tile pitch (floats), padded for float4
#define XR    37         // x-tile rows
#define HP    (TX + 3)   // 131  hist-tile pitch (u64)
#define HR    (TY + 3)   // 35   hist-tile rows
#define NG    33         // 4-pixel groups per hist row (last group is width 3)
#define OPLANE (OUT * OUT)
#define HTY   (TY / 2)

#define XS_BYTES  (XR * XP2 * 4)                  // 20128, 16B-aligned
#define SMEM_BYTES (XS_BYTES + HR * HP * 8)       // ~55.5 KB -> 4 CTAs/SM

typedef unsigned long long u64;
typedef unsigned int       u32;

// predicated packed add: if (pm == P) acc += v  (two fp32 lanes at once)
#define PRED_ADD2(acc, pm, P, v)                                              \
    asm("{ .reg .pred p; setp.eq.u32 p, %1, %2; @p add.rn.f32x2 %0, %0, %3; }" \
        : "+l"(acc) : "r"(pm), "n"(P), "l"(v))

#define ADD2(d, a, b)                                                         \
    asm("add.rn.f32x2 %0, %1, %2;" : "=l"(d) : "l"(a), "l"(b))

#define FMA2(d, a, b, c)                                                      \
    asm("fma.rn.f32x2 %0, %1, %2, %3;" : "=l"(d) : "l"(a), "l"(b), "l"(c))

// route one hist row (4 packed pixels) into rs[4] (accumulating)
static __device__ __forceinline__ void accum_row(const u64* __restrict__ p, u64 rs[4]) {
#pragma unroll
    for (int j = 0; j < 4; ++j) {
        u64 h  = p[j];
        u32 pm = (u32)h & 3u;           // pair index in low 2 bits of lo lane
        PRED_ADD2(rs[0], pm, 0, h);
        PRED_ADD2(rs[1], pm, 1, h);
        PRED_ADD2(rs[2], pm, 2, h);
        PRED_ADD2(rs[3], pm, 3, h);
    }
}

// mag/octant/pack from gradients
static __device__ __forceinline__ u64 pack_grad(float dx, float dy) {
    float sq = dx * dx + dy * dy;
    float sg = fmaxf(sq, 1.17549435e-38f);
    float rs_;
    asm("rsqrt.approx.f32 %0, %1;" : "=f"(rs_) : "f"(sg));
    float mag = sq * rs_;

    // octant of atan2(dy,dx) via sign bits + |dy|>|dx|; tie rules match
    // strict-> first-occurrence argmax of the 8 cosine projections.
    u32 bx = __float_as_uint(dx);
    u32 by = __float_as_uint(dy);
    u32 b2 = by >> 31;
    u32 b1 = (bx ^ by) >> 31;
    u32 c  = (fabsf(dy) > fabsf(dx)) ? 1u : 0u;
    u32 b0 = c ^ b1;
    u32 idx = (b2 << 2) | (b1 << 1) | b0;

    u32 magb = __float_as_uint(mag) & 0xFFFFFFFCu;
    u32 pm   = idx >> 1;
    u32 lo, hi;
    if (idx & 1) { lo = pm;        hi = magb; }
    else         { lo = magb | pm; hi = 0u;   }
    return ((u64)hi << 32) | lo;
}

__global__ __launch_bounds__(256)
void sift_fused9_kernel(const float* __restrict__ x, float* __restrict__ out)
{
    extern __shared__ char smem[];
    float* xs = (float*)smem;
    u64*   hs = (u64*)(smem + XS_BYTES);

    const int tid = threadIdx.x;
    const int ox0 = blockIdx.x * TX;
    const int oy0 = blockIdx.y * TY;

    // ---- phase 1: load x tile (cols gx = ox0-4+c, rows gy = oy0-3+r), zero-padded
    const bool ld_interior = (ox0 >= 4) && (ox0 <= IMG - 132) &&
                             (oy0 >= 3) && (oy0 <= IMG - 34);
    if (ld_interior) {
        const float* xb = x + (oy0 - 3) * IMG + (ox0 - 4);   // 16B-aligned
#pragma unroll 5
        for (int e = tid; e < XR * 34; e += 256) {
            int r  = e / 34;
            int c4 = e - r * 34;
            float4 v = *(const float4*)(xb + r * IMG + 4 * c4);
            *(float4*)&xs[r * XP2 + 4 * c4] = v;
        }
    } else {
        for (int e = tid; e < XR * XP2; e += 256) {
            int r  = e / XP2;
            int c  = e - r * XP2;
            int gy = oy0 - 3 + r;
            int gx = ox0 - 4 + c;
            float v = 0.0f;
            if ((unsigned)gy < (unsigned)IMG && (unsigned)gx < (unsigned)IMG)
                v = x[gy * IMG + gx];
            xs[r * XP2 + c] = v;
        }
    }
    __syncthreads();

    // ---- phase 2: 4-pixel groups; 6 LDS.128 per group, shared column sums.
    // Pixel (hy, hx+k), k=0..3: center xs col hx+2+k; taps xs cols hx+1..hx+6.
    // Loads cover xs cols hx..hx+7 (two aligned float4 per row).
    const bool h_interior = (ox0 >= 2) && (ox0 + TX + 2 < IMG) &&
                            (oy0 >= 2) && (oy0 + TY + 2 < IMG);
    for (int e = tid; e < HR * NG; e += 256) {
        int hy = e / NG;
        int g  = e - hy * NG;
        int hx = g * 4;

        const float* pb = xs + hy * XP2 + hx;
        float S[6], D[6];
        {
            float4 L0 = *(const float4*)(pb);
            float4 R0 = *(const float4*)(pb + 4);
            float4 L1 = *(const float4*)(pb + XP2);
            float4 R1 = *(const float4*)(pb + XP2 + 4);
            float4 L2 = *(const float4*)(pb + 2 * XP2);
            float4 R2 = *(const float4*)(pb + 2 * XP2 + 4);
            float t0[6] = { L0.y, L0.z, L0.w, R0.x, R0.y, R0.z };
            float t1[6] = { L1.y, L1.z, L1.w, R1.x, R1.y, R1.z };
            float t2[6] = { L2.y, L2.z, L2.w, R2.x, R2.y, R2.z };
#pragma unroll
            for (int j = 0; j < 6; ++j) {
                S[j] = t0[j] + 2.0f * t1[j] + t2[j];
                D[j] = t2[j] - t0[j];
            }
        }

        u64 pv[4];
#pragma unroll
        for (int k = 0; k < 4; ++k) {
            float dx = S[k + 2] - S[k];
            float dy = D[k] + 2.0f * D[k + 1] + D[k + 2];
            pv[k] = pack_grad(dx, dy);
        }

        if (!h_interior) {
            int gy = oy0 - 2 + hy;
            bool gyok = (unsigned)gy < (unsigned)IMG;
#pragma unroll
            for (int k = 0; k < 4; ++k) {
                int gx = ox0 - 2 + hx + k;
                if (!(gyok && (unsigned)gx < (unsigned)IMG)) pv[k] = 0ull;
            }
        }

        u64* hp = hs + hy * HP + hx;
        hp[0] = pv[0];
        hp[1] = pv[1];
        hp[2] = pv[2];
        if (hx + 3 < HP) hp[3] = pv[3];   // last group of each row is width 3
    }
    __syncthreads();

    // ---- phase 3: 4x4 box sum, vertical sliding window, 4 packed-pair channels
    const int tx   = tid & (TX - 1);
    const int q    = tid >> 7;              // 0/1 -> tile half in y
    const int ox   = ox0 + tx;
    const int oy_s = oy0 + q * HTY;
    const bool oxok = (ox < OUT);
    const u64* hb = hs + tx;
    const int hy0 = q * HTY;

    const u64 NEG1 = 0xBF800000BF800000ull;  // {-1.0f, -1.0f}

    u64 row[4][4];
    u64 acc[4];
#pragma unroll
    for (int pp = 0; pp < 4; ++pp) acc[pp] = 0ull;
#pragma unroll
    for (int k = 0; k < 4; ++k) {
#pragma unroll
        for (int pp = 0; pp < 4; ++pp) row[k][pp] = 0ull;
        accum_row(hb + (hy0 + k) * HP, row[k]);
#pragma unroll
        for (int pp = 0; pp < 4; ++pp) ADD2(acc[pp], acc[pp], row[k][pp]);
    }

#pragma unroll 4
    for (int i = 0; i < HTY; ++i) {
        int oy = oy_s + i;
        if (oxok && oy < OUT) {
            int base = oy * OUT + ox;
#pragma unroll
            for (int pp = 0; pp < 4; ++pp) {
                u32 lo = (u32)acc[pp];
                u32 hi = (u32)(acc[pp] >> 32);
                out[(2 * pp)     * OPLANE + base] = __uint_as_float(lo);
                out[(2 * pp + 1) * OPLANE + base] = __uint_as_float(hi);
            }
        }
        if (i < HTY - 1) {
            u64 nr[4];
#pragma unroll
            for (int pp = 0; pp < 4; ++pp) nr[pp] = 0ull;
            accum_row(hb + (hy0 + 4 + i) * HP, nr);
            const int k = i & 3;
#pragma unroll
            for (int pp = 0; pp < 4; ++pp) {
                u64 t;
                ADD2(t, acc[pp], nr[pp]);            // acc + new
                FMA2(acc[pp], row[k][pp], NEG1, t);  // - old
                row[k][pp] = nr[pp];
            }
        }
    }
}

extern "C" void kernel_launch(void* const* d_in, const int* in_sizes, int n_in,
                              void* d_out, int out_size)
{
    (void)in_sizes; (void)n_in; (void)out_size;
    const float* x = (const float*)d_in[0];
    float* out = (float*)d_out;
    cudaFuncSetAttribute(sift_fused9_kernel,
                         cudaFuncAttributeMaxDynamicSharedMemorySize, SMEM_BYTES);
    dim3 grid((OUT + TX - 1) / TX, (OUT + TY - 1) / TY);  // 33 x 129
    sift_fused9_kernel<<<grid, 256, SMEM_BYTES>>>(x, out);
}